// round 5
// baseline (speedup 1.0000x reference)
#include <cuda_runtime.h>

#define HH    8
#define DD    128
#define NEXP  4
#define MAXL  16384
#define MAXS  8
#define MAXSN (MAXS * NEXP)
#define NBLK  592

// ---- scratch (device globals; zero-initialized; no allocation allowed) ----
__device__ int      g_sel_e [2 * MAXL];
__device__ float    g_sel_v [2 * MAXL];
__device__ int      g_lrank [2 * MAXL];
__device__ int      g_sample[MAXL];
__device__ int      g_blkcnt [MAXSN * NBLK];   // [bucket][block]
__device__ int      g_blkbase[MAXSN * NBLK];   // exclusive scan over blocks
__device__ int      g_offs  [MAXSN + 1];
__device__ int      g_barcnt[2];               // arrival counters (self-reset)
__device__ unsigned g_gen   [2];               // monotonic generation counters

// ---------------------------------------------------------------------------
// Generation-counter grid barrier: last arriver resets the count then bumps
// the generation; others spin on the generation change. Monotonic across
// graph replays -> no reset race, no stale-counter deadlock.
// ---------------------------------------------------------------------------
__device__ __forceinline__ void grid_barrier(int i)
{
    __syncthreads();
    __threadfence();
    if (threadIdx.x == 0) {
        unsigned gen = ((volatile unsigned*)g_gen)[i];
        int old = atomicAdd(&g_barcnt[i], 1);
        if (old == (int)gridDim.x - 1) {
            g_barcnt[i] = 0;
            __threadfence();
            atomicAdd(&g_gen[i], 1);           // release
        } else {
            while (((volatile unsigned*)g_gen)[i] == gen) { __nanosleep(32); }
        }
    }
    __syncthreads();
    __threadfence();
}

// ---------------------------------------------------------------------------
// Fused persistent kernel: route (A) -> scan/offsets (B) -> scatter (C)
// ---------------------------------------------------------------------------
__global__ void __launch_bounds__(256, 4) fused_all(
    const float* __restrict__ q, const float* __restrict__ k, const float* __restrict__ v,
    const float* __restrict__ gk, const float* __restrict__ beta,
    const float* __restrict__ e_in, const int* __restrict__ cu,
    int L, int S,
    float* __restrict__ o_q, float* __restrict__ o_k, float* __restrict__ o_v,
    float* __restrict__ o_gk, float* __restrict__ o_beta,
    float* __restrict__ o_e, float* __restrict__ o_mask,
    float* __restrict__ o_off, float* __restrict__ o_state,
    float* __restrict__ o_gs)
{
    const int b     = blockIdx.x;
    const int tid   = threadIdx.x;
    const int lane  = tid & 31;
    const int warp  = tid >> 5;
    const int nwarp = blockDim.x >> 5;           // 8
    const int SN    = S * NEXP;

    const int chunk = (L + NBLK - 1) / NBLK;     // 28 for L=16384
    const int t0 = b * chunk;
    const int t1 = min(L, t0 + chunk);

    __shared__ int cnt[MAXSN];
    __shared__ int s_tot[MAXSN];
    if (tid < MAXSN) cnt[tid] = 0;
    __syncthreads();

    // ---------------- Phase A: routing + within-block bucket ranks ---------
    if (warp == 0) {
        unsigned lt = (1u << lane) - 1u;
        for (int base = t0; base < t1; base += 32) {
            int t = base + lane;
            bool act = (t < t1);
            int b0 = -1, b1 = -1, s = 0;
            if (act) {
                float4 xv = *(const float4*)(e_in + (size_t)t * NEXP);
                float x[NEXP] = {xv.x, xv.y, xv.z, xv.w};
                float m = fmaxf(fmaxf(x[0], x[1]), fmaxf(x[2], x[3]));
                float ssum = 0.0f;
#pragma unroll
                for (int i = 0; i < NEXP; i++) { x[i] = expf(x[i] - m); ssum += x[i]; }
                float inv = 1.0f / ssum;
#pragma unroll
                for (int i = 0; i < NEXP; i++) x[i] *= inv;

                b0 = 0; float v0 = x[0];
#pragma unroll
                for (int i = 1; i < NEXP; i++) if (x[i] > v0) { v0 = x[i]; b0 = i; }
                float v1 = -1e30f;
#pragma unroll
                for (int i = 0; i < NEXP; i++) if (i != b0 && x[i] > v1) { v1 = x[i]; b1 = i; }

                while (s + 1 < S && t >= cu[s + 1]) s++;

                *(float4*)(o_e + (size_t)t * NEXP) = make_float4(x[0], x[1], x[2], x[3]);
                float mk[NEXP];
#pragma unroll
                for (int i = 0; i < NEXP; i++) mk[i] = (i == b0 || i == b1) ? 1.0f : 0.0f;
                *(float4*)(o_mask + (size_t)t * NEXP) = make_float4(mk[0], mk[1], mk[2], mk[3]);

                g_sel_e[2 * t]     = b0;  g_sel_v[2 * t]     = v0;
                g_sel_e[2 * t + 1] = b1;  g_sel_v[2 * t + 1] = v1;
                g_sample[t] = s;
            }
            int bk0 = act ? s * NEXP + b0 : -1;
            int bk1 = act ? s * NEXP + b1 : -1;

            for (int B = 0; B < SN; B++) {
                int basec = cnt[B];
                unsigned msk = __ballot_sync(0xffffffffu, bk0 == B || bk1 == B);
                if (bk0 == B) g_lrank[2 * t]     = basec + __popc(msk & lt);
                if (bk1 == B) g_lrank[2 * t + 1] = basec + __popc(msk & lt);
                __syncwarp();
                if (lane == 0) cnt[B] = basec + __popc(msk);
                __syncwarp();
            }
        }
    }
    __syncthreads();
    if (tid < SN) g_blkcnt[tid * NBLK + b] = cnt[tid];

    grid_barrier(0);

    // ---------------- Phase B: cross-block scan + offsets (block 0) --------
    if (b == 0) {
        for (int B = warp; B < SN; B += nwarp) {        // 8 warps x 4 buckets
            int carry = 0;
            for (int base = 0; base < NBLK; base += 32) {
                int blk = base + lane;
                int val = (blk < NBLK) ? g_blkcnt[B * NBLK + blk] : 0;
                int incl = val;
#pragma unroll
                for (int off = 1; off < 32; off <<= 1) {
                    int y = __shfl_up_sync(0xffffffffu, incl, off);
                    if (lane >= off) incl += y;
                }
                if (blk < NBLK) g_blkbase[B * NBLK + blk] = carry + incl - val;
                carry += __shfl_sync(0xffffffffu, incl, 31);
            }
            if (lane == 0) { s_tot[B] = carry; o_state[B] = (float)carry; }
        }
        __syncthreads();
        if (tid == 0) {
            int acc = 0;
            g_offs[0] = 0;
            o_off[0] = 0.0f;
            for (int i = 0; i < SN; i++) {
                acc += s_tot[i];
                g_offs[i + 1] = acc;
                o_off[i + 1] = (float)acc;
            }
        }
    }

    grid_barrier(1);

    // ---------------- Phase C: DRAM-bound scatter ---------------------------
    const int ROW = HH * DD;                 // 1024 floats = 256 float4
    const int i = tid;

    for (int t = t0; t < t1; t++) {
        int e0 = g_sel_e[2 * t], e1 = g_sel_e[2 * t + 1];
        int s  = g_sample[t];
        float w0 = g_sel_v[2 * t], w1 = g_sel_v[2 * t + 1];
        int bk0 = s * NEXP + e0, bk1 = s * NEXP + e1;
        long p0 = (long)g_offs[bk0] + g_blkbase[bk0 * NBLK + b] + g_lrank[2 * t];
        long p1 = (long)g_offs[bk1] + g_blkbase[bk1 * NBLK + b] + g_lrank[2 * t + 1];

        const float4* qs = (const float4*)(q + (size_t)t * ROW);
        const float4* ks = (const float4*)(k + (size_t)t * ROW);
        const float4* vs = (const float4*)(v + (size_t)t * ROW);

        float4* qd0 = (float4*)(o_q + (size_t)p0 * ROW);
        float4* qd1 = (float4*)(o_q + (size_t)p1 * ROW);
        float4* kd0 = (float4*)(o_k + (size_t)p0 * ROW);
        float4* kd1 = (float4*)(o_k + (size_t)p1 * ROW);
        float4* vd0 = (float4*)(o_v + (size_t)p0 * ROW);
        float4* vd1 = (float4*)(o_v + (size_t)p1 * ROW);

        float4 a  = __ldcs(qs + i);
        float4 bb = __ldcs(ks + i);
        float4 c  = __ldcs(vs + i);

        __stcs(qd0 + i, make_float4(a.x * w0, a.y * w0, a.z * w0, a.w * w0));
        __stcs(qd1 + i, make_float4(a.x * w1, a.y * w1, a.z * w1, a.w * w1));
        __stcs(kd0 + i, make_float4(bb.x * w0, bb.y * w0, bb.z * w0, bb.w * w0));
        __stcs(kd1 + i, make_float4(bb.x * w1, bb.y * w1, bb.z * w1, bb.w * w1));
        __stcs(vd0 + i, c);
        __stcs(vd1 + i, c);

        if (i < HH) {
            float g  = gk[(size_t)t * HH + i];
            float bt = beta[(size_t)t * HH + i];
            o_gk[(size_t)p0 * HH + i]   = g;
            o_gk[(size_t)p1 * HH + i]   = g;
            o_beta[(size_t)p0 * HH + i] = bt;
            o_beta[(size_t)p1 * HH + i] = bt;
        }
        if (i == 0) {
            o_gs[p0] = (float)t;
            o_gs[p1] = (float)t;
        }
    }
}

// ---------------------------------------------------------------------------
extern "C" void kernel_launch(void* const* d_in, const int* in_sizes, int n_in,
                              void* d_out, int out_size)
{
    const float* q    = (const float*)d_in[0];
    const float* k    = (const float*)d_in[1];
    const float* v    = (const float*)d_in[2];
    const float* gk   = (const float*)d_in[3];
    const float* beta = (const float*)d_in[4];
    const float* e    = (const float*)d_in[5];
    const int*   cu   = (const int*)d_in[6];

    int L = in_sizes[0] / (HH * DD);
    int S = in_sizes[6] - 1;

    float* out = (float*)d_out;
    size_t LKHD = (size_t)L * 2 * HH * DD;
    float* o_q     = out;
    float* o_k     = o_q + LKHD;
    float* o_v     = o_k + LKHD;
    float* o_gk    = o_v + LKHD;
    float* o_beta  = o_gk + (size_t)L * 2 * HH;
    float* o_e     = o_beta + (size_t)L * 2 * HH;
    float* o_mask  = o_e + (size_t)L * NEXP;
    float* o_off   = o_mask + (size_t)L * NEXP;
    float* o_state = o_off + (size_t)(S * NEXP + 1);
    float* o_gs    = o_state + (size_t)(S * NEXP);

    fused_all<<<NBLK, 256>>>(q, k, v, gk, beta, e, cu, L, S,
                             o_q, o_k, o_v, o_gk, o_beta,
                             o_e, o_mask, o_off, o_state, o_gs);
}